// round 5
// baseline (speedup 1.0000x reference)
#include <cuda_runtime.h>
#include <cuda_bf16.h>
#include <cstdint>

#define NTOK 32768
#define DDIM 128
#define KHEADS 16

// ---------------- scratch (__device__ globals; no runtime allocation) ----------------
static __device__ __align__(16) __nv_bfloat16 g_Xb1[NTOK * DDIM];
static __device__ __align__(16) __nv_bfloat16 g_Xb2[NTOK * DDIM];
static __device__ __align__(16) __nv_bfloat16 g_Wb1[KHEADS * DDIM * DDIM]; // [k][e][d] (W^T)
static __device__ __align__(16) __nv_bfloat16 g_Wb2[KHEADS * DDIM * DDIM];
static __device__ __align__(16) float g_P2[KHEADS * NTOK];                 // part2 + bias, fp32

// ---------------- helpers ----------------
__device__ __forceinline__ uint32_t smem_u32(const void* p) {
    uint32_t a;
    asm("{ .reg .u64 t; cvta.to.shared.u64 t, %1; cvt.u32.u64 %0, t; }" : "=r"(a) : "l"(p));
    return a;
}

#define CP_ASYNC16(dst, src) \
    asm volatile("cp.async.cg.shared.global [%0], [%1], 16;" :: "r"(dst), "l"(src) : "memory")
#define CP_COMMIT() asm volatile("cp.async.commit_group;" ::: "memory")
#define CP_WAIT(N)  asm volatile("cp.async.wait_group %0;" :: "n"(N) : "memory")

#define LDSM_X4(r0, r1, r2, r3, addr) \
    asm volatile("ldmatrix.sync.aligned.m8n8.x4.shared.b16 {%0,%1,%2,%3}, [%4];" \
                 : "=r"(r0), "=r"(r1), "=r"(r2), "=r"(r3) : "r"(addr))
#define LDSM_X2(r0, r1, addr) \
    asm volatile("ldmatrix.sync.aligned.m8n8.x2.shared.b16 {%0,%1}, [%2];" \
                 : "=r"(r0), "=r"(r1) : "r"(addr))

#define MMA_BF16(c, a, b0v, b1v) \
    asm volatile("mma.sync.aligned.m16n8k16.row.col.f32.bf16.bf16.f32 " \
                 "{%0,%1,%2,%3}, {%4,%5,%6,%7}, {%8,%9}, {%0,%1,%2,%3};" \
                 : "+f"((c)[0]), "+f"((c)[1]), "+f"((c)[2]), "+f"((c)[3]) \
                 : "r"((a)[0]), "r"((a)[1]), "r"((a)[2]), "r"((a)[3]), \
                   "r"(b0v), "r"(b1v))

// ---------------- smem layout of main kernel ----------------
// X tiles: 128 rows x 128 bf16 cols, row stride padded to 272B (conflict-free ldmatrix).
#define ROWB   272
#define TILEB  34816              // 128 * 272
#define SM_X1  0
#define SM_X2  TILEB
#define SM_W   (2 * TILEB)        // + buf*(2*TILEB) ; side0 = WT1, side1 = WT2
#define SM_TOT (2 * TILEB + 2 * 2 * TILEB)   // 208896 B

// ================= prep kernels =================

__global__ void __launch_bounds__(256) k_convert_x(const float* __restrict__ x1,
                                                   const float* __restrict__ x2) {
    const int M = NTOK * DDIM / 4;
    int i = blockIdx.x * blockDim.x + threadIdx.x;
    if (i >= 2 * M) return;
    const float* src = (i < M) ? x1 : x2;
    __nv_bfloat16* dst = (i < M) ? g_Xb1 : g_Xb2;
    int j = (i < M) ? i : i - M;
    float4 v = reinterpret_cast<const float4*>(src)[j];
    __nv_bfloat162 lo = __floats2bfloat162_rn(v.x, v.y);
    __nv_bfloat162 hi = __floats2bfloat162_rn(v.z, v.w);
    uint2 pk;
    pk.x = *reinterpret_cast<uint32_t*>(&lo);
    pk.y = *reinterpret_cast<uint32_t*>(&hi);
    reinterpret_cast<uint2*>(dst)[j] = pk;
}

// g_Wb[k][e][d] = W[k][d][e] as bf16 (transpose + convert), 32x32 smem tiles.
__global__ void k_convert_w(const float* __restrict__ W1, const float* __restrict__ W2) {
    __shared__ float t[32][33];
    int k = blockIdx.z;
    int which = blockIdx.y >> 2;
    int ety = blockIdx.y & 3;
    int dtx = blockIdx.x;
    const float* src = which ? W2 : W1;
    __nv_bfloat16* dst = which ? g_Wb2 : g_Wb1;
    #pragma unroll
    for (int r = 0; r < 32; r += 8) {
        int d = dtx * 32 + threadIdx.y + r;
        int e = ety * 32 + threadIdx.x;
        t[threadIdx.y + r][threadIdx.x] = src[k * 16384 + d * 128 + e];
    }
    __syncthreads();
    #pragma unroll
    for (int r = 0; r < 32; r += 8) {
        int e = ety * 32 + threadIdx.y + r;
        int d = dtx * 32 + threadIdx.x;
        dst[k * 16384 + e * 128 + d] = __float2bfloat16(t[threadIdx.x][threadIdx.y + r]);
    }
}

// part2[k][n] = x_cat[n] . V[k] + b[k]   (fp32 — precision-critical)
__global__ void __launch_bounds__(256) k_part2(const float* __restrict__ x1,
                                               const float* __restrict__ x2,
                                               const float* __restrict__ V,
                                               const float* __restrict__ b) {
    int n = blockIdx.x * blockDim.x + threadIdx.x;
    float acc[KHEADS];
    #pragma unroll
    for (int k = 0; k < KHEADS; k++) acc[k] = __ldg(&b[k]);
    const float4* r1 = reinterpret_cast<const float4*>(x1 + (size_t)n * DDIM);
    const float4* r2 = reinterpret_cast<const float4*>(x2 + (size_t)n * DDIM);
    for (int c4 = 0; c4 < 32; c4++) {
        float4 xv = r1[c4];
        #pragma unroll
        for (int k = 0; k < KHEADS; k++) {
            float4 vv = __ldg(reinterpret_cast<const float4*>(V + k * 256 + c4 * 4));
            acc[k] = fmaf(xv.x, vv.x, acc[k]);
            acc[k] = fmaf(xv.y, vv.y, acc[k]);
            acc[k] = fmaf(xv.z, vv.z, acc[k]);
            acc[k] = fmaf(xv.w, vv.w, acc[k]);
        }
    }
    for (int c4 = 0; c4 < 32; c4++) {
        float4 xv = r2[c4];
        #pragma unroll
        for (int k = 0; k < KHEADS; k++) {
            float4 vv = __ldg(reinterpret_cast<const float4*>(V + k * 256 + 128 + c4 * 4));
            acc[k] = fmaf(xv.x, vv.x, acc[k]);
            acc[k] = fmaf(xv.y, vv.y, acc[k]);
            acc[k] = fmaf(xv.z, vv.z, acc[k]);
            acc[k] = fmaf(xv.w, vv.w, acc[k]);
        }
    }
    #pragma unroll
    for (int k = 0; k < KHEADS; k++) g_P2[k * NTOK + n] = acc[k];
}

// ================= main HMMA kernel =================
// 256 CTAs x 128 rows; 8 warps, warp = 16 rows x full 128 e-cols.
// A-frags (X) live in registers for all 16 heads; W double-buffered via cp.async.

__device__ __forceinline__ void copy_w_buf(uint32_t sb, int buf, int k, int tid) {
    uint32_t dbase = sb + SM_W + (uint32_t)buf * (2 * TILEB);
    const __nv_bfloat16* s1 = g_Wb1 + (size_t)k * 16384;
    const __nv_bfloat16* s2 = g_Wb2 + (size_t)k * 16384;
    #pragma unroll
    for (int it = 0; it < 16; it++) {
        int idx = tid + it * 256;            // 0..4095
        int side = idx >> 11;
        int c = idx & 2047;
        int row = c >> 4, ch = c & 15;
        uint32_t dst = dbase + (uint32_t)side * TILEB + row * ROWB + ch * 16;
        const __nv_bfloat16* src = (side ? s2 : s1) + row * 128 + ch * 8;
        CP_ASYNC16(dst, src);
    }
}

__global__ void __launch_bounds__(256, 1) k_main(float* __restrict__ out) {
    extern __shared__ char smem[];
    uint32_t sb = smem_u32(smem);
    int tid = threadIdx.x, wid = tid >> 5, lid = tid & 31;
    int n0 = blockIdx.x * 128;

    // --- X tiles -> smem (group 0) ---
    {
        const __nv_bfloat16* s1 = g_Xb1 + (size_t)n0 * DDIM;
        const __nv_bfloat16* s2 = g_Xb2 + (size_t)n0 * DDIM;
        #pragma unroll
        for (int it = 0; it < 16; it++) {
            int idx = tid + it * 256;
            int side = idx >> 11;
            int c = idx & 2047;
            int row = c >> 4, ch = c & 15;
            uint32_t dst = sb + (uint32_t)side * TILEB + row * ROWB + ch * 16;
            const __nv_bfloat16* src = (side ? s2 : s1) + row * 128 + ch * 8;
            CP_ASYNC16(dst, src);
        }
        CP_COMMIT();
    }
    // --- W[0] -> buf0 (group 1) ---
    copy_w_buf(sb, 0, 0, tid);
    CP_COMMIT();

    CP_WAIT(1);          // X ready
    __syncthreads();

    // --- preload A fragments: 8 k-steps x 2 sides, kept in regs for all heads ---
    int l15 = lid & 15;
    uint32_t aoff = (uint32_t)(wid * 16 + l15) * ROWB + (uint32_t)(lid >> 4) * 16;
    uint32_t a1f[8][4], a2f[8][4];
    #pragma unroll
    for (int s = 0; s < 8; s++) {
        LDSM_X4(a1f[s][0], a1f[s][1], a1f[s][2], a1f[s][3], sb + SM_X1 + aoff + s * 32);
        LDSM_X4(a2f[s][0], a2f[s][1], a2f[s][2], a2f[s][3], sb + SM_X2 + aoff + s * 32);
    }

    // B-frag lane offset within a WT tile
    uint32_t boff = (uint32_t)(l15 & 7) * ROWB + (uint32_t)(l15 >> 3) * 16;

    for (int k = 0; k < KHEADS; k++) {
        if (k < KHEADS - 1) {
            copy_w_buf(sb, (k + 1) & 1, k + 1, tid);
            CP_COMMIT();
            CP_WAIT(1);      // buf[k&1] ready
        } else {
            CP_WAIT(0);
        }
        __syncthreads();

        uint32_t wbase = sb + SM_W + (uint32_t)(k & 1) * (2 * TILEB);
        uint32_t b1base = wbase + boff;
        uint32_t b2base = wbase + TILEB + boff;

        float dA = 0.f, dB = 0.f, s1A = 0.f, s1B = 0.f, s2A = 0.f, s2B = 0.f;

        for (int ec = 0; ec < 16; ec += 2) {
            float c1a[4] = {0,0,0,0}, c1b[4] = {0,0,0,0};
            float c2a[4] = {0,0,0,0}, c2b[4] = {0,0,0,0};
            uint32_t pa = b1base + (uint32_t)ec * (8 * ROWB);
            uint32_t pb = pa + (8 * ROWB);
            uint32_t qa = b2base + (uint32_t)ec * (8 * ROWB);
            uint32_t qb = qa + (8 * ROWB);
            #pragma unroll
            for (int s = 0; s < 8; s++) {
                uint32_t u0, u1, v0, v1, w0, w1, x0, x1;
                LDSM_X2(u0, u1, pa + s * 32);
                LDSM_X2(v0, v1, pb + s * 32);
                LDSM_X2(w0, w1, qa + s * 32);
                LDSM_X2(x0, x1, qb + s * 32);
                MMA_BF16(c1a, a1f[s], u0, u1);
                MMA_BF16(c1b, a1f[s], v0, v1);
                MMA_BF16(c2a, a2f[s], w0, w1);
                MMA_BF16(c2b, a2f[s], x0, x1);
            }
            // rows g (elems 0,1) / g+8 (elems 2,3)
            dA  = fmaf(c1a[0], c2a[0], dA);  dA  = fmaf(c1a[1], c2a[1], dA);
            dA  = fmaf(c1b[0], c2b[0], dA);  dA  = fmaf(c1b[1], c2b[1], dA);
            dB  = fmaf(c1a[2], c2a[2], dB);  dB  = fmaf(c1a[3], c2a[3], dB);
            dB  = fmaf(c1b[2], c2b[2], dB);  dB  = fmaf(c1b[3], c2b[3], dB);
            s1A = fmaf(c1a[0], c1a[0], s1A); s1A = fmaf(c1a[1], c1a[1], s1A);
            s1A = fmaf(c1b[0], c1b[0], s1A); s1A = fmaf(c1b[1], c1b[1], s1A);
            s1B = fmaf(c1a[2], c1a[2], s1B); s1B = fmaf(c1a[3], c1a[3], s1B);
            s1B = fmaf(c1b[2], c1b[2], s1B); s1B = fmaf(c1b[3], c1b[3], s1B);
            s2A = fmaf(c2a[0], c2a[0], s2A); s2A = fmaf(c2a[1], c2a[1], s2A);
            s2A = fmaf(c2b[0], c2b[0], s2A); s2A = fmaf(c2b[1], c2b[1], s2A);
            s2B = fmaf(c2a[2], c2a[2], s2B); s2B = fmaf(c2a[3], c2a[3], s2B);
            s2B = fmaf(c2b[2], c2b[2], s2B); s2B = fmaf(c2b[3], c2b[3], s2B);
        }

        // quad reduction (lanes g*4 .. g*4+3 hold the 8 cols of rows g, g+8)
        #pragma unroll
        for (int m = 1; m <= 2; m <<= 1) {
            dA  += __shfl_xor_sync(0xFFFFFFFFu, dA,  m);
            dB  += __shfl_xor_sync(0xFFFFFFFFu, dB,  m);
            s1A += __shfl_xor_sync(0xFFFFFFFFu, s1A, m);
            s1B += __shfl_xor_sync(0xFFFFFFFFu, s1B, m);
            s2A += __shfl_xor_sync(0xFFFFFFFFu, s2A, m);
            s2B += __shfl_xor_sync(0xFFFFFFFFu, s2B, m);
        }

        if ((lid & 3) == 0) {
            int g = lid >> 2;
            int nA = n0 + wid * 16 + g;
            int nB = nA + 8;
            float vA = dA / (fmaxf(sqrtf(s1A), 1e-8f) * fmaxf(sqrtf(s2A), 1e-8f))
                     + g_P2[k * NTOK + nA];
            float vB = dB / (fmaxf(sqrtf(s1B), 1e-8f) * fmaxf(sqrtf(s2B), 1e-8f))
                     + g_P2[k * NTOK + nB];
            out[(size_t)nA * KHEADS + k] = fmaxf(vA, 0.f);
            out[(size_t)nB * KHEADS + k] = fmaxf(vB, 0.f);
        }
        __syncthreads();   // buf[k&1] free before it is overwritten at k+1
    }
}

// ================= launch =================
extern "C" void kernel_launch(void* const* d_in, const int* in_sizes, int n_in,
                              void* d_out, int out_size) {
    const float* x1 = (const float*)d_in[0];
    const float* x2 = (const float*)d_in[1];
    const float* W1 = (const float*)d_in[2];
    const float* W2 = (const float*)d_in[3];
    const float* V  = (const float*)d_in[4];
    const float* b  = (const float*)d_in[5];
    float* out = (float*)d_out;

    {
        int chunks = 2 * NTOK * DDIM / 4;
        k_convert_x<<<(chunks + 255) / 256, 256>>>(x1, x2);
    }
    k_convert_w<<<dim3(4, 8, KHEADS), dim3(32, 8)>>>(W1, W2);
    k_part2<<<NTOK / 256, 256>>>(x1, x2, V, b);

    cudaFuncSetAttribute(k_main, cudaFuncAttributeMaxDynamicSharedMemorySize, SM_TOT);
    k_main<<<NTOK / 128, 256, SM_TOT>>>(out);
}